// round 16
// baseline (speedup 1.0000x reference)
#include <cuda_runtime.h>
#include <math.h>
#include <stdint.h>

#define B_  16
#define N_  307
#define T_  12
#define C_  64
#define TC_ 768
#define NH_ 32
#define DK_ 24
#define DV_ 8
#define NORM_ 0.2041241452319315f

__device__ __forceinline__ float sg(float x){ return 1.f/(1.f+__expf(-x)); }

// ---------------- scratch offsets (floats) ----------------
constexpr long ELT = (long)B_*N_*T_*C_;
constexpr long G4  = 4L*B_*N_*C_;
constexpr long O_A    = 0;
constexpr long O_RS   = O_A    + 94272;
constexpr long O_W    = O_RS   + 512;
constexpr long O_EM   = O_W    + 5*4096;
constexpr long O_U3   = O_EM   + 58944;
constexpr long O_U4   = O_U3   + 58944;
constexpr long O_P    = O_U4   + 58944;
constexpr long O_S3   = O_P    + 58944;
constexpr long O_S4   = O_S3   + 256;
constexpr long O_C34  = O_S4   + 256;
constexpr long O_ATTE = O_C34  + 2304;
constexpr long O_COEFE= O_ATTE + (long)B_*N_*144;
constexpr long O_BASE = O_COEFE+ 58944;
constexpr long O_R    = O_BASE + 12288;
constexpr long O_G0   = O_R    + 147456;
constexpr long O_SN   = O_G0   + 64;
constexpr long O_AL   = O_SN   + ELT;
constexpr long O_AR   = O_AL   + ELT;
constexpr long O_ATTN = O_AR   + ELT;
constexpr long O_XW   = O_ATTN + (long)B_*C_*144;
constexpr long O_X0N  = O_XW   + ELT;
constexpr long O_QKV  = O_X0N  + ELT;              // 4912*1792
constexpr long O_Z0   = O_QKV  + 8802304;
constexpr long O_Z    = O_Z0   + G4;
constexpr long O_Z2   = O_Z    + G4;
constexpr long O_ZW   = O_Z2   + G4;
constexpr long O_ATT3 = O_ZW   + G4;
constexpr long O_X1S  = O_ATT3 + 4096;
constexpr long O_XG   = O_X1S  + ELT;
constexpr long O_XL   = O_XG   + ELT;
constexpr long O_XE   = O_XL   + ELT;
constexpr long O_T1   = O_XE   + ELT;
constexpr long SCR    = O_T1   + ELT;
__device__ float g_s[SCR];

__device__ __forceinline__ uint32_t f2tf32(float v){
    uint32_t u;
    asm("cvt.rna.tf32.f32 %0, %1;" : "=r"(u) : "f"(v));
    return u;
}

#define MMA_TF32(acc, a, b) \
    asm volatile( \
        "mma.sync.aligned.m16n8k8.row.col.f32.tf32.tf32.f32 " \
        "{%0,%1,%2,%3}, {%4,%5,%6,%7}, {%8,%9}, {%0,%1,%2,%3};" \
        : "+f"((acc)[0]), "+f"((acc)[1]), "+f"((acc)[2]), "+f"((acc)[3]) \
        : "r"((a)[0]), "r"((a)[1]), "r"((a)[2]), "r"((a)[3]), \
          "r"((b)[0]), "r"((b)[1]))

// ---------------- tf32 mma.sync QKV GEMM (proven) ----------------
__global__ void __launch_bounds__(256, 2)
k_qkv_mma(const float* __restrict__ x,
          const float* __restrict__ wq, const float* __restrict__ wk,
          const float* __restrict__ wv,
          const float* __restrict__ bq, const float* __restrict__ bk,
          const float* __restrict__ bv,
          float* __restrict__ Cp)
{
    __shared__ float As[2][16][136];
    __shared__ float Bs[2][16][72];
    const int nt = blockIdx.x, mt = blockIdx.y;
    const float* Bsrc; const float* bias; int ldb; int ncol0;
    if (nt < 12)      { Bsrc = wq; bias = bq; ldb = 768; ncol0 = nt*64; }
    else if (nt < 24) { Bsrc = wk; bias = bk; ldb = 768; ncol0 = (nt-12)*64; }
    else              { Bsrc = wv; bias = bv; ldb = 256; ncol0 = (nt-24)*64; }
    const int tid = threadIdx.x;
    const int warp = tid >> 5, lane = tid & 31;
    const int wm = warp >> 1, wn = warp & 1;
    const int qr = lane >> 2, qc = lane & 3;
    const int arow = tid >> 1, acol = (tid & 1) * 8;
    const int brow = tid >> 4, bcol = (tid & 15) * 4;
    const int gm = mt*128 + arow;
    float aR[8]; float4 bR;

    auto loadA = [&](int k0){
        if (gm < 4912) {
            const float4* p = (const float4*)(x + (long)gm*768 + k0 + acol);
            float4 t0 = p[0], t1 = p[1];
            aR[0]=t0.x; aR[1]=t0.y; aR[2]=t0.z; aR[3]=t0.w;
            aR[4]=t1.x; aR[5]=t1.y; aR[6]=t1.z; aR[7]=t1.w;
        } else {
            #pragma unroll
            for (int i = 0; i < 8; i++) aR[i] = 0.f;
        }
    };
    auto loadB = [&](int k0){
        bR = *(const float4*)(Bsrc + (long)(k0 + brow)*ldb + ncol0 + bcol);
    };
    auto sts = [&](int buf){
        #pragma unroll
        for (int i = 0; i < 8; i++)
            As[buf][acol+i][arow] = __uint_as_float(f2tf32(aR[i]));
        float4 c;
        c.x = __uint_as_float(f2tf32(bR.x)); c.y = __uint_as_float(f2tf32(bR.y));
        c.z = __uint_as_float(f2tf32(bR.z)); c.w = __uint_as_float(f2tf32(bR.w));
        *(float4*)&Bs[buf][brow][bcol] = c;
    };

    loadA(0); loadB(0);
    sts(0);
    __syncthreads();

    float acc[2][4][4];
    #pragma unroll
    for (int mi = 0; mi < 2; mi++)
        #pragma unroll
        for (int ni = 0; ni < 4; ni++)
            #pragma unroll
            for (int j = 0; j < 4; j++) acc[mi][ni][j] = 0.f;

    int buf = 0;
    for (int k0 = 0; k0 < 768; k0 += 16) {
        bool nxt = (k0 + 16 < 768);
        if (nxt) { loadA(k0+16); loadB(k0+16); }
        #pragma unroll
        for (int ks = 0; ks < 2; ks++) {
            int kb = ks * 8;
            uint32_t a[2][4], b[4][2];
            #pragma unroll
            for (int mi = 0; mi < 2; mi++) {
                int mrow = wm*32 + mi*16;
                a[mi][0] = __float_as_uint(As[buf][kb+qc  ][mrow+qr  ]);
                a[mi][1] = __float_as_uint(As[buf][kb+qc  ][mrow+qr+8]);
                a[mi][2] = __float_as_uint(As[buf][kb+qc+4][mrow+qr  ]);
                a[mi][3] = __float_as_uint(As[buf][kb+qc+4][mrow+qr+8]);
            }
            #pragma unroll
            for (int ni = 0; ni < 4; ni++) {
                int ncol = wn*32 + ni*8;
                b[ni][0] = __float_as_uint(Bs[buf][kb+qc  ][ncol+qr]);
                b[ni][1] = __float_as_uint(Bs[buf][kb+qc+4][ncol+qr]);
            }
            #pragma unroll
            for (int mi = 0; mi < 2; mi++)
                #pragma unroll
                for (int ni = 0; ni < 4; ni++)
                    MMA_TF32(acc[mi][ni], a[mi], b[ni]);
        }
        if (nxt) { sts(buf^1); __syncthreads(); buf ^= 1; }
    }

    #pragma unroll
    for (int mi = 0; mi < 2; mi++) {
        #pragma unroll
        for (int ni = 0; ni < 4; ni++) {
            int row = mt*128 + wm*32 + mi*16 + qr;
            int lcol = wn*32 + ni*8 + qc*2;
            float b0 = bias[ncol0 + lcol], b1 = bias[ncol0 + lcol + 1];
            long gcol = (long)nt*64 + lcol;
            if (row < 4912)
                *(float2*)&Cp[(long)row*1792 + gcol] =
                    make_float2(acc[mi][ni][0] + b0, acc[mi][ni][1] + b1);
            if (row + 8 < 4912)
                *(float2*)&Cp[(long)(row+8)*1792 + gcol] =
                    make_float2(acc[mi][ni][2] + b0, acc[mi][ni][3] + b1);
        }
    }
}

// ------- tf32 adjacency GEMM: C[b] = A(307x307) @ Bm[b](307x768) -------
__global__ void __launch_bounds__(256, 2)
k_adj_mma768(const float* __restrict__ A, const float* __restrict__ Bm,
             float* __restrict__ Cm)
{
    constexpr int COLS = 768;
    __shared__ float As[2][16][136];
    __shared__ float Bs[2][16][72];
    const float* Bp = Bm + (long)blockIdx.z * N_ * COLS;
    float*       Cp = Cm + (long)blockIdx.z * N_ * COLS;
    const int m0 = blockIdx.y * 128, n0 = blockIdx.x * 64;
    const int tid = threadIdx.x;
    const int warp = tid >> 5, lane = tid & 31;
    const int wm = warp >> 1, wn = warp & 1;
    const int qr = lane >> 2, qc = lane & 3;
    const int arow = tid >> 1, acol = (tid & 1) * 8;
    const int brow = tid >> 4, bcol = (tid & 15) * 4;
    const int gm = m0 + arow;
    float aR[8], bRv[4];

    auto loadA = [&](int k0){
        #pragma unroll
        for (int i = 0; i < 8; i++) {
            int gk = k0 + acol + i;
            aR[i] = (gm < N_ && gk < N_) ? A[gm*N_ + gk] : 0.f;
        }
    };
    auto loadB = [&](int k0){
        int gk = k0 + brow;
        if (gk < N_) {
            float4 t = *(const float4*)(Bp + (long)gk*COLS + n0 + bcol);
            bRv[0]=t.x; bRv[1]=t.y; bRv[2]=t.z; bRv[3]=t.w;
        } else { bRv[0]=bRv[1]=bRv[2]=bRv[3]=0.f; }
    };
    auto sts = [&](int buf){
        #pragma unroll
        for (int i = 0; i < 8; i++)
            As[buf][acol+i][arow] = __uint_as_float(f2tf32(aR[i]));
        float4 c;
        c.x = __uint_as_float(f2tf32(bRv[0])); c.y = __uint_as_float(f2tf32(bRv[1]));
        c.z = __uint_as_float(f2tf32(bRv[2])); c.w = __uint_as_float(f2tf32(bRv[3]));
        *(float4*)&Bs[buf][brow][bcol] = c;
    };

    loadA(0); loadB(0);
    sts(0);
    __syncthreads();

    float acc[2][4][4];
    #pragma unroll
    for (int mi = 0; mi < 2; mi++)
        #pragma unroll
        for (int ni = 0; ni < 4; ni++)
            #pragma unroll
            for (int j = 0; j < 4; j++) acc[mi][ni][j] = 0.f;

    int buf = 0;
    #pragma unroll 1
    for (int k0 = 0; k0 < N_; k0 += 16) {
        bool nxt = (k0 + 16 < N_);
        if (nxt) { loadA(k0+16); loadB(k0+16); }
        #pragma unroll
        for (int ks = 0; ks < 2; ks++) {
            int kb = ks * 8;
            uint32_t a[2][4], b[4][2];
            #pragma unroll
            for (int mi = 0; mi < 2; mi++) {
                int mrow = wm*32 + mi*16;
                a[mi][0] = __float_as_uint(As[buf][kb+qc  ][mrow+qr  ]);
                a[mi][1] = __float_as_uint(As[buf][kb+qc  ][mrow+qr+8]);
                a[mi][2] = __float_as_uint(As[buf][kb+qc+4][mrow+qr  ]);
                a[mi][3] = __float_as_uint(As[buf][kb+qc+4][mrow+qr+8]);
            }
            #pragma unroll
            for (int ni = 0; ni < 4; ni++) {
                int ncol = wn*32 + ni*8;
                b[ni][0] = __float_as_uint(Bs[buf][kb+qc  ][ncol+qr]);
                b[ni][1] = __float_as_uint(Bs[buf][kb+qc+4][ncol+qr]);
            }
            #pragma unroll
            for (int mi = 0; mi < 2; mi++)
                #pragma unroll
                for (int ni = 0; ni < 4; ni++)
                    MMA_TF32(acc[mi][ni], a[mi], b[ni]);
        }
        if (nxt) { sts(buf^1); __syncthreads(); buf ^= 1; }
    }

    #pragma unroll
    for (int mi = 0; mi < 2; mi++) {
        #pragma unroll
        for (int ni = 0; ni < 4; ni++) {
            int row = m0 + wm*32 + mi*16 + qr;
            int col = n0 + wn*32 + ni*8 + qc*2;
            if (row < N_)
                *(float2*)&Cp[(long)row*COLS + col] =
                    make_float2(acc[mi][ni][0], acc[mi][ni][1]);
            if (row + 8 < N_)
                *(float2*)&Cp[(long)(row+8)*COLS + col] =
                    make_float2(acc[mi][ni][2], acc[mi][ni][3]);
        }
    }
}

// ------- fused adjacency GEMM + ODE step (COLS=64) -------
// Zout = 0.5*sg(alpha3)* (A@Zin) + att3*Zin + ZW + Z0 - 2*Zin;  also -> x1s
__global__ void __launch_bounds__(256, 2)
k_adj_step(const float* __restrict__ A, const float* __restrict__ Zin,
           const float* __restrict__ ZW, const float* __restrict__ Z0,
           const float* __restrict__ att3, const float* __restrict__ alpha3,
           float* __restrict__ Zout, float* __restrict__ x1s, int step)
{
    __shared__ float As[2][16][136];
    __shared__ float Bs[2][16][72];
    const int zb = blockIdx.z;              // g*16 + b
    const int g = zb >> 4, bb = zb & 15;
    const long zBase = (long)zb * N_ * 64;
    const float* Bp = Zin + zBase;
    const int m0 = blockIdx.y * 128, n0 = 0;
    const int tid = threadIdx.x;
    const int warp = tid >> 5, lane = tid & 31;
    const int wm = warp >> 1, wn = warp & 1;
    const int qr = lane >> 2, qc = lane & 3;
    const int arow = tid >> 1, acol = (tid & 1) * 8;
    const int brow = tid >> 4, bcol = (tid & 15) * 4;
    const int gm = m0 + arow;
    float aR[8], bRv[4];

    auto loadA = [&](int k0){
        #pragma unroll
        for (int i = 0; i < 8; i++) {
            int gk = k0 + acol + i;
            aR[i] = (gm < N_ && gk < N_) ? A[gm*N_ + gk] : 0.f;
        }
    };
    auto loadB = [&](int k0){
        int gk = k0 + brow;
        if (gk < N_) {
            float4 t = *(const float4*)(Bp + (long)gk*64 + n0 + bcol);
            bRv[0]=t.x; bRv[1]=t.y; bRv[2]=t.z; bRv[3]=t.w;
        } else { bRv[0]=bRv[1]=bRv[2]=bRv[3]=0.f; }
    };
    auto sts = [&](int buf){
        #pragma unroll
        for (int i = 0; i < 8; i++)
            As[buf][acol+i][arow] = __uint_as_float(f2tf32(aR[i]));
        float4 c;
        c.x = __uint_as_float(f2tf32(bRv[0])); c.y = __uint_as_float(f2tf32(bRv[1]));
        c.z = __uint_as_float(f2tf32(bRv[2])); c.w = __uint_as_float(f2tf32(bRv[3]));
        *(float4*)&Bs[buf][brow][bcol] = c;
    };

    loadA(0); loadB(0);
    sts(0);
    __syncthreads();

    float acc[2][4][4];
    #pragma unroll
    for (int mi = 0; mi < 2; mi++)
        #pragma unroll
        for (int ni = 0; ni < 4; ni++)
            #pragma unroll
            for (int j = 0; j < 4; j++) acc[mi][ni][j] = 0.f;

    int buf = 0;
    #pragma unroll 1
    for (int k0 = 0; k0 < N_; k0 += 16) {
        bool nxt = (k0 + 16 < N_);
        if (nxt) { loadA(k0+16); loadB(k0+16); }
        #pragma unroll
        for (int ks = 0; ks < 2; ks++) {
            int kb = ks * 8;
            uint32_t a[2][4], b[4][2];
            #pragma unroll
            for (int mi = 0; mi < 2; mi++) {
                int mrow = wm*32 + mi*16;
                a[mi][0] = __float_as_uint(As[buf][kb+qc  ][mrow+qr  ]);
                a[mi][1] = __float_as_uint(As[buf][kb+qc  ][mrow+qr+8]);
                a[mi][2] = __float_as_uint(As[buf][kb+qc+4][mrow+qr  ]);
                a[mi][3] = __float_as_uint(As[buf][kb+qc+4][mrow+qr+8]);
            }
            #pragma unroll
            for (int ni = 0; ni < 4; ni++) {
                int ncol = wn*32 + ni*8;
                b[ni][0] = __float_as_uint(Bs[buf][kb+qc  ][ncol+qr]);
                b[ni][1] = __float_as_uint(Bs[buf][kb+qc+4][ncol+qr]);
            }
            #pragma unroll
            for (int mi = 0; mi < 2; mi++)
                #pragma unroll
                for (int ni = 0; ni < 4; ni++)
                    MMA_TF32(acc[mi][ni], a[mi], b[ni]);
        }
        if (nxt) { sts(buf^1); __syncthreads(); buf ^= 1; }
    }

    #pragma unroll
    for (int mi = 0; mi < 2; mi++) {
        #pragma unroll
        for (int ni = 0; ni < 4; ni++) {
            int col = n0 + wn*32 + ni*8 + qc*2;
            float2 a3 = *(const float2*)(att3 + (long)zb*64 + col);
            #pragma unroll
            for (int h = 0; h < 2; h++) {
                int row = m0 + wm*32 + mi*16 + qr + h*8;
                if (row >= N_) continue;
                long idx = zBase + (long)row*64 + col;
                float2 zv = *(const float2*)(Zin + idx);
                float2 zw = *(const float2*)(ZW  + idx);
                float2 z0 = *(const float2*)(Z0  + idx);
                float aa = 0.5f*sg(alpha3[g*N_ + row]);
                float o0 = aa*acc[mi][ni][h*2+0] + a3.x*zv.x + zw.x + z0.x - 2.f*zv.x;
                float o1 = aa*acc[mi][ni][h*2+1] + a3.y*zv.y + zw.y + z0.y - 2.f*zv.y;
                *(float2*)&Zout[idx] = make_float2(o0, o1);
                *(float2*)&x1s[(((long)bb*N_+row)*12 + step*4 + g)*64 + col] =
                    make_float2(o0, o1);
            }
        }
    }
}

// ------- tf32 K=64 linear GEMM with fused A-producer / epilogue -------
template<int AMODE, int EMODE>
__global__ void __launch_bounds__(256, 2)
k_lin64(const float* __restrict__ A0, const float* __restrict__ A1,
        const float* __restrict__ A2, const float* __restrict__ A3,
        const float* __restrict__ clipv,
        long sA, const float* __restrict__ Bw, long sB,
        float* __restrict__ Cm, long sC, int M,
        const float* __restrict__ bias, const float* __restrict__ T1e)
{
    __shared__ float As[2][16][136];
    __shared__ float Bs[2][16][72];
    const long za = (long)blockIdx.z * sA;
    const float* Bp = Bw + (long)blockIdx.z * sB;
    float*       Cp = Cm + (long)blockIdx.z * sC;
    const int m0 = blockIdx.y * 128;
    const int tid = threadIdx.x;
    const int warp = tid >> 5, lane = tid & 31;
    const int wm = warp >> 1, wn = warp & 1;
    const int qr = lane >> 2, qc = lane & 3;
    const int arow = tid >> 1, acol = (tid & 1) * 8;
    const int brow = tid >> 4, bcol = (tid & 15) * 4;
    const int gm = m0 + arow;
    float cv = 0.f;
    if (AMODE == 1) cv = clipv[0];
    float aR[8]; float4 bRv;

    auto loadA = [&](int k0){
        if (gm < M) {
            long off = za + (long)gm*64 + k0 + acol;
            if (AMODE == 0) {
                float4 v0 = *(const float4*)(A0 + off);
                float4 v1 = *(const float4*)(A0 + off + 4);
                aR[0]=v0.x; aR[1]=v0.y; aR[2]=v0.z; aR[3]=v0.w;
                aR[4]=v1.x; aR[5]=v1.y; aR[6]=v1.z; aR[7]=v1.w;
            } else if (AMODE == 1) {
                float4 s0 = *(const float4*)(A0 + off);
                float4 s1 = *(const float4*)(A0 + off + 4);
                float4 n0 = *(const float4*)(A1 + off);
                float4 n1 = *(const float4*)(A1 + off + 4);
                float sv[8] = {s0.x,s0.y,s0.z,s0.w,s1.x,s1.y,s1.z,s1.w};
                float nv[8] = {n0.x,n0.y,n0.z,n0.w,n1.x,n1.y,n1.z,n1.w};
                #pragma unroll
                for (int i = 0; i < 8; i++)
                    aR[i] = fmaxf(fminf(sv[i], nv[i]+cv), nv[i]-cv);
            } else {
                float4 g0 = *(const float4*)(A0 + off);
                float4 g1 = *(const float4*)(A0 + off + 4);
                float4 l0 = *(const float4*)(A1 + off);
                float4 l1 = *(const float4*)(A1 + off + 4);
                float4 e0 = *(const float4*)(A2 + off);
                float4 e1 = *(const float4*)(A2 + off + 4);
                float4 r0 = *(const float4*)(A3 + off);
                float4 r1 = *(const float4*)(A3 + off + 4);
                float gv[8] = {g0.x,g0.y,g0.z,g0.w,g1.x,g1.y,g1.z,g1.w};
                float lv[8] = {l0.x,l0.y,l0.z,l0.w,l1.x,l1.y,l1.z,l1.w};
                float ev[8] = {e0.x,e0.y,e0.z,e0.w,e1.x,e1.y,e1.z,e1.w};
                float rv[8] = {r0.x,r0.y,r0.z,r0.w,r1.x,r1.y,r1.z,r1.w};
                #pragma unroll
                for (int i = 0; i < 8; i++){
                    float sa = sg(gv[i]), sb = sg(lv[i]), se = sg(ev[i]);
                    aR[i] = (gv[i]*(sb+se) + lv[i]*(se+sa) + ev[i]*(sb+sa)
                             + rv[i]) * (1.f/6.f);
                }
            }
        } else {
            #pragma unroll
            for (int i = 0; i < 8; i++) aR[i] = 0.f;
        }
    };
    auto loadB = [&](int k0){
        bRv = *(const float4*)(Bp + (long)(k0 + brow)*64 + bcol);
    };
    auto sts = [&](int buf){
        #pragma unroll
        for (int i = 0; i < 8; i++)
            As[buf][acol+i][arow] = __uint_as_float(f2tf32(aR[i]));
        float4 c;
        c.x = __uint_as_float(f2tf32(bRv.x)); c.y = __uint_as_float(f2tf32(bRv.y));
        c.z = __uint_as_float(f2tf32(bRv.z)); c.w = __uint_as_float(f2tf32(bRv.w));
        *(float4*)&Bs[buf][brow][bcol] = c;
    };

    loadA(0); loadB(0);
    sts(0);
    __syncthreads();

    float acc[2][4][4];
    #pragma unroll
    for (int mi = 0; mi < 2; mi++)
        #pragma unroll
        for (int ni = 0; ni < 4; ni++)
            #pragma unroll
            for (int j = 0; j < 4; j++) acc[mi][ni][j] = 0.f;

    int buf = 0;
    #pragma unroll
    for (int k0 = 0; k0 < 64; k0 += 16) {
        bool nxt = (k0 + 16 < 64);
        if (nxt) { loadA(k0+16); loadB(k0+16); }
        #pragma unroll
        for (int ks = 0; ks < 2; ks++) {
            int kb = ks * 8;
            uint32_t a[2][4], b[4][2];
            #pragma unroll
            for (int mi = 0; mi < 2; mi++) {
                int mrow = wm*32 + mi*16;
                a[mi][0] = __float_as_uint(As[buf][kb+qc  ][mrow+qr  ]);
                a[mi][1] = __float_as_uint(As[buf][kb+qc  ][mrow+qr+8]);
                a[mi][2] = __float_as_uint(As[buf][kb+qc+4][mrow+qr  ]);
                a[mi][3] = __float_as_uint(As[buf][kb+qc+4][mrow+qr+8]);
            }
            #pragma unroll
            for (int ni = 0; ni < 4; ni++) {
                int ncol = wn*32 + ni*8;
                b[ni][0] = __float_as_uint(Bs[buf][kb+qc  ][ncol+qr]);
                b[ni][1] = __float_as_uint(Bs[buf][kb+qc+4][ncol+qr]);
            }
            #pragma unroll
            for (int mi = 0; mi < 2; mi++)
                #pragma unroll
                for (int ni = 0; ni < 4; ni++)
                    MMA_TF32(acc[mi][ni], a[mi], b[ni]);
        }
        if (nxt) { sts(buf^1); __syncthreads(); buf ^= 1; }
    }

    #pragma unroll
    for (int mi = 0; mi < 2; mi++) {
        #pragma unroll
        for (int ni = 0; ni < 4; ni++) {
            int col = wn*32 + ni*8 + qc*2;
            float b0 = bias ? bias[col] : 0.f, b1 = bias ? bias[col+1] : 0.f;
            #pragma unroll
            for (int h = 0; h < 2; h++) {
                int row = m0 + wm*32 + mi*16 + qr + h*8;
                if (row >= M) continue;
                float v0 = acc[mi][ni][h*2+0] + b0;
                float v1 = acc[mi][ni][h*2+1] + b1;
                long off = (long)row*64 + col;
                if (EMODE == 1) {
                    float2 t = *(const float2*)(T1e + (long)row*64 + col);
                    v0 = fmaxf(sg(t.x) + v0, 0.f);
                    v1 = fmaxf(sg(t.y) + v1, 0.f);
                }
                *(float2*)&Cp[off] = make_float2(v0, v1);
            }
        }
    }
}

// ---------------- fp32 SGEMM (tiny P gemm, cols=12) ----------------
__global__ void k_gemm(const float* __restrict__ A, int lda, long sA,
                       const float* __restrict__ Bm, int ldb, long sB,
                       float* __restrict__ Cm, int ldc, long sC,
                       int M, int K, int cols, const float* __restrict__ bias)
{
    __shared__ __align__(16) float As[16][64];
    __shared__ __align__(16) float Bs[16][64];
    const float* Ap = A  + (long)blockIdx.z * sA;
    const float* Bp = Bm + (long)blockIdx.z * sB;
    float*       Cp = Cm + (long)blockIdx.z * sC;
    int m0 = blockIdx.y * 64, n0 = blockIdx.x * 64;
    int tid = threadIdx.x;
    int ty = tid >> 4, tx = tid & 15;
    int arow = tid >> 2, akq = (tid & 3) << 2;
    int brow = tid >> 4, bnq = (tid & 15) << 2;
    float acc[4][4] = {};
    for (int k0 = 0; k0 < K; k0 += 16) {
        int am = m0 + arow;
        #pragma unroll
        for (int i = 0; i < 4; i++) {
            int kk = k0 + akq + i;
            As[akq + i][arow] = (am < M && kk < K) ? Ap[(long)am * lda + kk] : 0.f;
        }
        int bk = k0 + brow;
        #pragma unroll
        for (int i = 0; i < 4; i++) {
            int bn = n0 + bnq + i;
            Bs[brow][bnq + i] = (bk < K && bn < cols) ? Bp[(long)bk * ldb + bn] : 0.f;
        }
        __syncthreads();
        #pragma unroll
        for (int k = 0; k < 16; k++) {
            float4 av = *(const float4*)&As[k][ty << 2];
            float4 bv = *(const float4*)&Bs[k][tx << 2];
            float ax[4] = {av.x, av.y, av.z, av.w};
            float bx[4] = {bv.x, bv.y, bv.z, bv.w};
            #pragma unroll
            for (int i = 0; i < 4; i++)
                #pragma unroll
                for (int j = 0; j < 4; j++)
                    acc[i][j] += ax[i] * bx[j];
        }
        __syncthreads();
    }
    #pragma unroll
    for (int i = 0; i < 4; i++) {
        int m = m0 + (ty << 2) + i;
        if (m >= M) continue;
        #pragma unroll
        for (int j = 0; j < 4; j++) {
            int n = n0 + (tx << 2) + j;
            if (n < cols) Cp[(long)m * ldc + n] = acc[i][j] + (bias ? bias[n] : 0.f);
        }
    }
}

// ---------------- small setup kernels ----------------
__global__ void k_Ars(const float* adj, const float* mask, float* A, float* rs){
    int n = blockIdx.x, t = threadIdx.x;
    __shared__ float red[256];
    float s = 0;
    for (int j = t; j < N_; j += 256){
        float v = adj[n*N_+j] + mask[n*N_+j];
        A[n*N_+j] = v;
        s += v;
    }
    red[t] = s;
    __syncthreads();
    for (int k = 128; k > 0; k >>= 1){
        if (t < k) red[t] += red[t+k];
        __syncthreads();
    }
    if (t == 0) rs[n] = red[0];
}
__global__ void k_W(const float* wn, const float* dn, const float* w3, const float* d3,
                    float* Wout){
    __shared__ float bufA[4096];
    __shared__ float bufB[4096];
    __shared__ float dd[64];
    int s = blockIdx.x;
    const float* w = (s == 0) ? wn : w3 + (s-1)*4096;
    const float* d = (s == 0) ? dn : d3 + (s-1)*64;
    int tid = threadIdx.x;
    for (int i = tid; i < 4096; i += 1024) bufA[i] = w[i];
    if (tid < 64) dd[tid] = fminf(fmaxf(d[tid], 0.f), 1.f);
    __syncthreads();
    int row = tid >> 4, j0 = (tid & 15) << 2;
    float a0[4] = {};
    for (int k = 0; k < 64; k++) {
        float wk = bufA[row*64 + k] * dd[k];
        #pragma unroll
        for (int j = 0; j < 4; j++) a0[j] += wk * bufA[(j0+j)*64 + k];
    }
    __syncthreads();
    #pragma unroll
    for (int j = 0; j < 4; j++) bufB[row*64 + j0 + j] = a0[j];
    __syncthreads();
    float a1[4] = {};
    for (int k = 0; k < 64; k++) {
        float m1 = bufB[row*64 + k];
        #pragma unroll
        for (int j = 0; j < 4; j++) a1[j] += m1 * bufB[k*64 + j0 + j];
    }
    __syncthreads();
    #pragma unroll
    for (int j = 0; j < 4; j++) bufA[row*64 + j0 + j] = a1[j];
    __syncthreads();
    float a2[4] = {};
    for (int k = 0; k < 64; k++) {
        float m2 = bufA[row*64 + k];
        #pragma unroll
        for (int j = 0; j < 4; j++) a2[j] += m2 * bufB[k*64 + j0 + j];
    }
    #pragma unroll
    for (int j = 0; j < 4; j++)
        Wout[s*4096 + row*64 + j0 + j] = 1.6f*bufB[row*64 + j0 + j] - 0.6f*a2[j];
}
__global__ void k_em(const float* __restrict__ x, const float* __restrict__ w3,
                     const float* __restrict__ w4,
                     float* em, float* u3, float* u4){
    __shared__ float xs[8][768];
    __shared__ float ems[8][12];
    int w = threadIdx.x >> 5, l = threadIdx.x & 31;
    int bn = blockIdx.x*8 + w;
    if (bn >= B_*N_) return;
    const float* xp = x + (long)bn*768;
    #pragma unroll
    for (int i = 0; i < 24; i++) xs[w][l + i*32] = xp[l + i*32];
    __syncwarp();
    if (l < 12) {
        float s = 0;
        #pragma unroll 8
        for (int c = 0; c < 64; c++) s += xs[w][l*64 + ((c + l) & 63)];
        s *= (1.f/64.f);
        ems[w][l] = s;
        em[bn*12 + l] = s;
    }
    __syncwarp();
    if (l < 12) {
        float s3 = 0, s4 = 0;
        #pragma unroll
        for (int tt = 0; tt < 12; tt++){ s3 += ems[w][tt]*w3[tt*12+l]; s4 += ems[w][tt]*w4[tt*12+l]; }
        u3[bn*12+l] = s3; u4[bn*12+l] = s4;
    }
}
__global__ void k_S(const float* u3, const float* u4, float* S3, float* S4, float* C34){
    int b = blockIdx.x, tid = threadIdx.x;
    int o = tid/12, p = tid%12;
    float c = 0, s3 = 0, s4 = 0;
    for (int n = 0; n < N_; n++){
        float a = u3[(b*N_+n)*12+o], r = u4[(b*N_+n)*12+p];
        c += a*r;
        if (p == 0) s3 += a;
        if (o == 0) s4 += r;
    }
    C34[b*144+tid] = c;
    if (p == 0) S3[b*12+o] = s3;
    if (o == 0) S4[b*12+p] = s4;
}
__global__ void k_attE(const float* u3, const float* u4, const float* S3, const float* S4,
                       const float* C34, const float* P, const float* em,
                       const float* alphaE, float* attE, float* coefE){
    int bn = blockIdx.x; int b = bn / N_; int n = bn % N_;
    int tid = threadIdx.x;
    int o = tid/12, p = tid%12;
    __shared__ float at[144], ems[12];
    float l = (float)N_*u3[bn*12+o]*u4[bn*12+p] + u3[bn*12+o]*S4[b*12+p]
            + S3[b*12+o]*u4[bn*12+p] + C34[b*144+tid];
    float a = sg(l);
    at[tid] = a; attE[(long)bn*144+tid] = a;
    if (tid < 12) ems[tid] = em[bn*12+tid];
    __syncthreads();
    if (tid < 12) {
        float wv = 0;
        #pragma unroll
        for (int oo = 0; oo < 12; oo++) wv += ems[oo]*at[oo*12+tid];
        coefE[bn*12+tid] = 0.5f*sg(alphaE[n])*P[bn*12+tid] + wv;
    }
}
__global__ void k_base(const float* coefE, const float* fw, float* base){
    int b = blockIdx.y, t = blockIdx.x, c = threadIdx.x;
    float s = 0;
    #pragma unroll 4
    for (int n = 0; n < N_; n++) s += fw[n*64+c] * coefE[(b*N_+n)*12+t];
    base[(b*12+t)*64+c] = s;
}
__global__ void k_R(const float* attE, const float* fw, float* R){
    int b = blockIdx.y, tp = blockIdx.x, c = threadIdx.x;
    float s = 0;
    #pragma unroll 4
    for (int n = 0; n < N_; n++) s += attE[((long)b*N_+n)*144+tp] * fw[n*64+c];
    R[((long)b*144+tp)*64+c] = s;
}
__global__ void k_g0(const float* fw, const float* alphaE, const float* rs, float* g0){
    int c = threadIdx.x; float s = 0;
    for (int n = 0; n < N_; n++) s += fw[n*64+c]*sg(alphaE[n])*rs[n];
    g0[c] = 0.5f*s;
}
__global__ void k_al(const float* x, const float* w3, const float* w4,
                     float* al, float* ar){
    __shared__ float w3s[144], w4s[144];
    int bn = blockIdx.x, c = threadIdx.x;
    for (int i = c; i < 144; i += 64){ w3s[i] = w3[i]; w4s[i] = w4[i]; }
    __syncthreads();
    float xr[12];
    const float* xp = x + (long)bn*768 + c;
    #pragma unroll
    for (int t = 0; t < 12; t++) xr[t] = xp[t*64];
    #pragma unroll
    for (int o = 0; o < 12; o++){
        float a = 0, r = 0;
        #pragma unroll
        for (int t = 0; t < 12; t++){ a += xr[t]*w3s[t*12+o]; r += xr[t]*w4s[t*12+o]; }
        al[((long)bn*12+o)*64+c] = a; ar[((long)bn*12+o)*64+c] = r;
    }
}
// attN rewrite: one block per batch b, 256 threads, register 3x12 tile.
__global__ void __launch_bounds__(256)
k_attN2(const float* __restrict__ al, const float* __restrict__ ar,
        float* __restrict__ attN){
    int b = blockIdx.x;
    int t = threadIdx.x;
    int c = t & 63, q = t >> 6;              // q: o-group [3q, 3q+2]
    __shared__ float als[768], ars[768];
    float acc[36];
    #pragma unroll
    for (int i = 0; i < 36; i++) acc[i] = 0.f;
    for (int n = 0; n < N_; n++){
        __syncthreads();
        const float* ap = al + (long)(b*N_+n)*768;
        const float* rp = ar + (long)(b*N_+n)*768;
        #pragma unroll
        for (int i = 0; i < 3; i++){
            als[t + i*256] = ap[t + i*256];
            ars[t + i*256] = rp[t + i*256];
        }
        __syncthreads();
        float av[3], rv[12];
        #pragma unroll
        for (int i = 0; i < 3; i++) av[i] = als[(q*3+i)*64 + c];
        #pragma unroll
        for (int j = 0; j < 12; j++) rv[j] = ars[j*64 + c];
        #pragma unroll
        for (int i = 0; i < 3; i++)
            #pragma unroll
            for (int j = 0; j < 12; j++)
                acc[i*12+j] += av[i]*rv[j];
    }
    #pragma unroll
    for (int i = 0; i < 3; i++)
        #pragma unroll
        for (int j = 0; j < 12; j++)
            attN[((long)b*64+c)*144 + (q*3+i)*12 + j] = sg(acc[i*12+j]);
}
__global__ void k_x0n(const float* x, const float* Sn, const float* xw,
                      const float* attN, const float* alphaN, float* x0n){
    int bn = blockIdx.x; int b = bn / N_, n = bn % N_;
    int c = threadIdx.x;
    __shared__ float xs[12][64];
    const float* xp = x + (long)bn*768;
    #pragma unroll
    for (int t = 0; t < 12; t++) xs[t][c] = xp[t*64+c];
    __syncthreads();
    float aN = 0.5f*sg(alphaN[n]);
    const float* an = attN + ((long)b*64+c)*144;
    #pragma unroll
    for (int o = 0; o < 12; o++){
        float tn = 0;
        #pragma unroll
        for (int p = 0; p < 12; p++) tn += an[o*12+p]*xs[p][c];
        long idx = (long)bn*768 + o*64 + c;
        x0n[idx] = aN*Sn[idx] + tn + xw[idx] - xs[o][c];
    }
}
__global__ void k_mhsa(const float* qkv, float* z0, float* z){
    int h = blockIdx.x, b = blockIdx.y;
    __shared__ __align__(16) float Ks[N_*DK_];
    __shared__ __align__(16) float Vs[N_*DV_];
    int tid = threadIdx.x;
    for (int i = tid; i < N_*DK_; i += 256){
        int n = i/DK_, d = i%DK_;
        Ks[i] = qkv[((long)b*N_+n)*1792 + 768 + h*DK_ + d];
    }
    for (int i = tid; i < N_*DV_; i += 256){
        int n = i/DV_, d = i%DV_;
        Vs[i] = qkv[((long)b*N_+n)*1792 + 1536 + h*DV_ + d];
    }
    __syncthreads();
    const float4* K4 = (const float4*)Ks;
    const float4* V4 = (const float4*)Vs;
    for (int r = 0; r < 2; r++){
        int n = tid + r*256;
        if (n >= N_) break;
        float qr[DK_];
        const float* qp = qkv + ((long)b*N_+n)*1792 + h*DK_;
        #pragma unroll
        for (int d = 0; d < DK_; d++) qr[d] = qp[d];
        float mmax = -1e30f, l = 0.f, acc[DV_] = {};
        for (int m = 0; m < N_; m++){
            float s = 0;
            #pragma unroll
            for (int i = 0; i < 6; i++){
                float4 kv = K4[m*6+i];
                s += qr[i*4+0]*kv.x + qr[i*4+1]*kv.y + qr[i*4+2]*kv.z + qr[i*4+3]*kv.w;
            }
            s *= NORM_;
            float nm = fmaxf(mmax, s);
            float e0 = __expf(mmax - nm);
            float e1 = __expf(s - nm);
            l = l*e0 + e1;
            float4 v0 = V4[m*2+0], v1 = V4[m*2+1];
            acc[0] = acc[0]*e0 + e1*v0.x; acc[1] = acc[1]*e0 + e1*v0.y;
            acc[2] = acc[2]*e0 + e1*v0.z; acc[3] = acc[3]*e0 + e1*v0.w;
            acc[4] = acc[4]*e0 + e1*v1.x; acc[5] = acc[5]*e0 + e1*v1.y;
            acc[6] = acc[6]*e0 + e1*v1.z; acc[7] = acc[7]*e0 + e1*v1.w;
            mmax = nm;
        }
        float inv = 1.f/l;
        #pragma unroll
        for (int j = 0; j < DV_; j++){
            int flat = h*DV_ + j;
            int g = flat >> 6, c = flat & 63;
            long idx = (((long)g*B_+b)*N_+n)*64 + c;
            float val = acc[j]*inv;
            z0[idx] = val; z[idx] = val;
        }
    }
}
__global__ void k_att3(const float* z, const float* w31, const float* w41, float* att3){
    int gb = blockIdx.x, c = threadIdx.x;
    float s = 0;
    const float* zp = z + (long)gb*N_*64 + c;
    #pragma unroll 4
    for (int n = 0; n < N_; n++){ float v = zp[n*64]; s += v*v; }
    att3[gb*64+c] = sg(w31[0]*w41[0]*s);
}
__global__ void k_xe(const float* em, const float* base, const float* g0,
                     const float* R, const float* fb, float* xe){
    int bm = blockIdx.x; int b = bm / N_;
    int c = threadIdx.x;
    float emr[12];
    #pragma unroll
    for (int t = 0; t < 12; t++) emr[t] = em[bm*12+t];
    float g0c = g0[c], fbc = fb[c];
    #pragma unroll
    for (int t = 0; t < 12; t++){
        float acc = base[(b*12+t)*64+c] + emr[t]*g0c + fbc;
        #pragma unroll
        for (int tp = 0; tp < 12; tp++)
            acc += emr[tp]*R[((long)b*144 + tp*12 + t)*64 + c];
        xe[((long)bm*12+t)*64+c] = acc;
    }
}

// ---------------- host ----------------
static void gemmF(const float* A, int lda, long sA, const float* B, int ldb, long sB,
                  float* C, int ldc, long sC, int M, int K, int cols,
                  const float* bias, int batch){
    dim3 g((cols+63)/64, (M+63)/64, batch);
    k_gemm<<<g, 256>>>(A, lda, sA, B, ldb, sB, C, ldc, sC, M, K, cols, bias);
}

extern "C" void kernel_launch(void* const* d_in, const int* in_sizes, int n_in,
                              void* d_out, int out_size){
    const float* x      = (const float*)d_in[0];
    const float* adj    = (const float*)d_in[1];
    const float* mask   = (const float*)d_in[2];
    const float* w3_12  = (const float*)d_in[3];
    const float* w4_12  = (const float*)d_in[4];
    const float* w3_1   = (const float*)d_in[5];
    const float* w4_1   = (const float*)d_in[6];
    const float* alphaN = (const float*)d_in[7];
    const float* w_n11  = (const float*)d_in[8];
    const float* d_n11  = (const float*)d_in[9];
    const float* alphaE = (const float*)d_in[10];
    const float* alpha3 = (const float*)d_in[11];
    const float* w_3    = (const float*)d_in[12];
    const float* d_3    = (const float*)d_in[13];
    const float* wq     = (const float*)d_in[14];
    const float* bq     = (const float*)d_in[15];
    const float* wk     = (const float*)d_in[16];
    const float* bk     = (const float*)d_in[17];
    const float* wv     = (const float*)d_in[18];
    const float* bv     = (const float*)d_in[19];
    const float* fc1w   = (const float*)d_in[20];
    const float* fc1b   = (const float*)d_in[21];
    const float* fc2w   = (const float*)d_in[22];
    const float* fc2b   = (const float*)d_in[23];
    const float* fcew   = (const float*)d_in[24];
    const float* fceb   = (const float*)d_in[25];
    const float* clip   = (const float*)d_in[26];
    float* out = (float*)d_out;

    float* S;
    cudaGetSymbolAddress((void**)&S, g_s);
    float *A = S+O_A, *RS = S+O_RS, *W = S+O_W, *EM = S+O_EM, *U3 = S+O_U3, *U4 = S+O_U4;
    float *P = S+O_P, *S3 = S+O_S3, *S4 = S+O_S4, *C34 = S+O_C34, *ATTE = S+O_ATTE;
    float *COEFE = S+O_COEFE, *BASE = S+O_BASE, *R = S+O_R, *G0 = S+O_G0, *SN = S+O_SN;
    float *AL = S+O_AL, *AR = S+O_AR, *ATTN = S+O_ATTN, *XW = S+O_XW, *X0N = S+O_X0N;
    float *QKV = S+O_QKV, *Z0 = S+O_Z0, *Z = S+O_Z, *Z2 = S+O_Z2;
    float *ZW = S+O_ZW, *ATT3 = S+O_ATT3, *X1S = S+O_X1S;
    float *XG = S+O_XG, *XL = S+O_XL, *XE = S+O_XE, *T1 = S+O_T1;

    const int MROWS = B_*N_*T_;               // 58944
    dim3 gLin(1, (MROWS+127)/128, 1);

    k_Ars<<<N_, 256>>>(adj, mask, A, RS);
    k_W<<<5, 1024>>>(w_n11, d_n11, w_3, d_3, W);
    k_em<<<(B_*N_+7)/8, 256>>>(x, w3_12, w4_12, EM, U3, U4);
    k_S<<<B_, 144>>>(U3, U4, S3, S4, C34);
    gemmF(A, N_, 0, EM, 12, (long)N_*12, P, 12, (long)N_*12, N_, N_, 12, nullptr, B_);
    k_attE<<<B_*N_, 144>>>(U3, U4, S3, S4, C34, P, EM, alphaE, ATTE, COEFE);
    k_base<<<dim3(12, B_), 64>>>(COEFE, fcew, BASE);
    k_R<<<dim3(144, B_), 64>>>(ATTE, fcew, R);
    k_g0<<<1, 64>>>(fcew, alphaE, RS, G0);
    k_adj_mma768<<<dim3(12, 3, 16), 256>>>(A, x, SN);
    k_lin64<0,0><<<gLin, 256>>>(x, nullptr, nullptr, nullptr, nullptr,
                                0, W, 0, XW, 0, MROWS, nullptr, nullptr);
    k_al<<<B_*N_, 64>>>(x, w3_12, w4_12, AL, AR);
    k_attN2<<<B_, 256>>>(AL, AR, ATTN);
    k_x0n<<<B_*N_, 64>>>(x, SN, XW, ATTN, alphaN, X0N);
    k_qkv_mma<<<dim3(28, 39), 256>>>(x, wq, wk, wv, bq, bk, bv, QKV);
    k_mhsa<<<dim3(NH_, B_), 256>>>(QKV, Z0, Z);
    float* Zbuf[2] = {Z, Z2};
    for (int step = 0; step < 3; step++){
        float* Zin  = Zbuf[step & 1];
        float* Zout = Zbuf[(step & 1) ^ 1];
        k_att3<<<64, 64>>>(Zin, w3_1, w4_1, ATT3);
        k_lin64<0,0><<<dim3(1, (B_*N_+127)/128, 4), 256>>>(
            Zin, nullptr, nullptr, nullptr, nullptr,
            16L*N_*64, W + 4096, 4096, ZW, 16L*N_*64, B_*N_, nullptr, nullptr);
        k_adj_step<<<dim3(1, 3, 64), 256>>>(A, Zin, ZW, Z0, ATT3, alpha3,
                                            Zout, X1S, step);
    }
    // XG = clip(X1S, X0N +- clip) @ fc1w + fc1b   (clip fused)
    k_lin64<1,0><<<gLin, 256>>>(X1S, X0N, nullptr, nullptr, clip,
                                0, fc1w, 0, XG, 0, MROWS, fc1b, nullptr);
    // XL = X0N @ fc1w + fc1b
    k_lin64<0,0><<<gLin, 256>>>(X0N, nullptr, nullptr, nullptr, nullptr,
                                0, fc1w, 0, XL, 0, MROWS, fc1b, nullptr);
    k_xe<<<B_*N_, 64>>>(EM, BASE, G0, R, fceb, XE);
    // T1 = x @ fc2w + fc2b
    k_lin64<0,0><<<gLin, 256>>>(x, nullptr, nullptr, nullptr, nullptr,
                                0, fc2w, 0, T1, 0, MROWS, fc2b, nullptr);
    // out = relu(sg(T1) + final1(XG,XL,XE,x) @ fc2w + fc2b)
    k_lin64<2,1><<<gLin, 256>>>(XG, XL, XE, x, nullptr,
                                0, fc2w, 0, out, 0, MROWS, fc2b, T1);
}

// round 17
// speedup vs baseline: 1.1113x; 1.1113x over previous
#include <cuda_runtime.h>
#include <math.h>
#include <stdint.h>

#define B_  16
#define N_  307
#define T_  12
#define C_  64
#define TC_ 768
#define NH_ 32
#define DK_ 24
#define DV_ 8
#define NORM_ 0.2041241452319315f

__device__ __forceinline__ float sg(float x){ return 1.f/(1.f+__expf(-x)); }

// ---------------- scratch offsets (floats) ----------------
constexpr long ELT = (long)B_*N_*T_*C_;
constexpr long G4  = 4L*B_*N_*C_;
constexpr long O_A    = 0;
constexpr long O_RS   = O_A    + 94272;
constexpr long O_W    = O_RS   + 512;
constexpr long O_EM   = O_W    + 5*4096;
constexpr long O_U3   = O_EM   + 58944;
constexpr long O_U4   = O_U3   + 58944;
constexpr long O_P    = O_U4   + 58944;
constexpr long O_S3   = O_P    + 58944;
constexpr long O_S4   = O_S3   + 256;
constexpr long O_C34  = O_S4   + 256;
constexpr long O_ATTE = O_C34  + 2304;
constexpr long O_COEFE= O_ATTE + (long)B_*N_*144;
constexpr long O_BASE = O_COEFE+ 58944;
constexpr long O_R    = O_BASE + 12288;
constexpr long O_G0   = O_R    + 147456;
constexpr long O_SN   = O_G0   + 64;
constexpr long O_AL   = O_SN   + ELT;
constexpr long O_AR   = O_AL   + ELT;
constexpr long O_ATTN = O_AR   + ELT;
constexpr long O_XW   = O_ATTN + (long)B_*C_*144;
constexpr long O_X0N  = O_XW   + ELT;
constexpr long O_QKV  = O_X0N  + ELT;              // 4912*1792
constexpr long O_Z0   = O_QKV  + 8802304;
constexpr long O_Z    = O_Z0   + G4;
constexpr long O_SZ   = O_Z    + G4;
constexpr long O_ZW   = O_SZ   + G4;
constexpr long O_ATT3 = O_ZW   + G4;
constexpr long O_X1S  = O_ATT3 + 4096;
constexpr long O_XG   = O_X1S  + ELT;
constexpr long O_XL   = O_XG   + ELT;
constexpr long O_XE   = O_XL   + ELT;
constexpr long O_T1   = O_XE   + ELT;
constexpr long SCR    = O_T1   + ELT;
__device__ float g_s[SCR];

__device__ __forceinline__ uint32_t f2tf32(float v){
    uint32_t u;
    asm("cvt.rna.tf32.f32 %0, %1;" : "=r"(u) : "f"(v));
    return u;
}

#define MMA_TF32(acc, a, b) \
    asm volatile( \
        "mma.sync.aligned.m16n8k8.row.col.f32.tf32.tf32.f32 " \
        "{%0,%1,%2,%3}, {%4,%5,%6,%7}, {%8,%9}, {%0,%1,%2,%3};" \
        : "+f"((acc)[0]), "+f"((acc)[1]), "+f"((acc)[2]), "+f"((acc)[3]) \
        : "r"((a)[0]), "r"((a)[1]), "r"((a)[2]), "r"((a)[3]), \
          "r"((b)[0]), "r"((b)[1]))

// ---------------- tf32 mma.sync QKV GEMM (proven) ----------------
__global__ void __launch_bounds__(256, 2)
k_qkv_mma(const float* __restrict__ x,
          const float* __restrict__ wq, const float* __restrict__ wk,
          const float* __restrict__ wv,
          const float* __restrict__ bq, const float* __restrict__ bk,
          const float* __restrict__ bv,
          float* __restrict__ Cp)
{
    __shared__ float As[2][16][136];
    __shared__ float Bs[2][16][72];
    const int nt = blockIdx.x, mt = blockIdx.y;
    const float* Bsrc; const float* bias; int ldb; int ncol0;
    if (nt < 12)      { Bsrc = wq; bias = bq; ldb = 768; ncol0 = nt*64; }
    else if (nt < 24) { Bsrc = wk; bias = bk; ldb = 768; ncol0 = (nt-12)*64; }
    else              { Bsrc = wv; bias = bv; ldb = 256; ncol0 = (nt-24)*64; }
    const int tid = threadIdx.x;
    const int warp = tid >> 5, lane = tid & 31;
    const int wm = warp >> 1, wn = warp & 1;
    const int qr = lane >> 2, qc = lane & 3;
    const int arow = tid >> 1, acol = (tid & 1) * 8;
    const int brow = tid >> 4, bcol = (tid & 15) * 4;
    const int gm = mt*128 + arow;
    float aR[8]; float4 bR;

    auto loadA = [&](int k0){
        if (gm < 4912) {
            const float4* p = (const float4*)(x + (long)gm*768 + k0 + acol);
            float4 t0 = p[0], t1 = p[1];
            aR[0]=t0.x; aR[1]=t0.y; aR[2]=t0.z; aR[3]=t0.w;
            aR[4]=t1.x; aR[5]=t1.y; aR[6]=t1.z; aR[7]=t1.w;
        } else {
            #pragma unroll
            for (int i = 0; i < 8; i++) aR[i] = 0.f;
        }
    };
    auto loadB = [&](int k0){
        bR = *(const float4*)(Bsrc + (long)(k0 + brow)*ldb + ncol0 + bcol);
    };
    auto sts = [&](int buf){
        #pragma unroll
        for (int i = 0; i < 8; i++)
            As[buf][acol+i][arow] = __uint_as_float(f2tf32(aR[i]));
        float4 c;
        c.x = __uint_as_float(f2tf32(bR.x)); c.y = __uint_as_float(f2tf32(bR.y));
        c.z = __uint_as_float(f2tf32(bR.z)); c.w = __uint_as_float(f2tf32(bR.w));
        *(float4*)&Bs[buf][brow][bcol] = c;
    };

    loadA(0); loadB(0);
    sts(0);
    __syncthreads();

    float acc[2][4][4];
    #pragma unroll
    for (int mi = 0; mi < 2; mi++)
        #pragma unroll
        for (int ni = 0; ni < 4; ni++)
            #pragma unroll
            for (int j = 0; j < 4; j++) acc[mi][ni][j] = 0.f;

    int buf = 0;
    for (int k0 = 0; k0 < 768; k0 += 16) {
        bool nxt = (k0 + 16 < 768);
        if (nxt) { loadA(k0+16); loadB(k0+16); }
        #pragma unroll
        for (int ks = 0; ks < 2; ks++) {
            int kb = ks * 8;
            uint32_t a[2][4], b[4][2];
            #pragma unroll
            for (int mi = 0; mi < 2; mi++) {
                int mrow = wm*32 + mi*16;
                a[mi][0] = __float_as_uint(As[buf][kb+qc  ][mrow+qr  ]);
                a[mi][1] = __float_as_uint(As[buf][kb+qc  ][mrow+qr+8]);
                a[mi][2] = __float_as_uint(As[buf][kb+qc+4][mrow+qr  ]);
                a[mi][3] = __float_as_uint(As[buf][kb+qc+4][mrow+qr+8]);
            }
            #pragma unroll
            for (int ni = 0; ni < 4; ni++) {
                int ncol = wn*32 + ni*8;
                b[ni][0] = __float_as_uint(Bs[buf][kb+qc  ][ncol+qr]);
                b[ni][1] = __float_as_uint(Bs[buf][kb+qc+4][ncol+qr]);
            }
            #pragma unroll
            for (int mi = 0; mi < 2; mi++)
                #pragma unroll
                for (int ni = 0; ni < 4; ni++)
                    MMA_TF32(acc[mi][ni], a[mi], b[ni]);
        }
        if (nxt) { sts(buf^1); __syncthreads(); buf ^= 1; }
    }

    #pragma unroll
    for (int mi = 0; mi < 2; mi++) {
        #pragma unroll
        for (int ni = 0; ni < 4; ni++) {
            int row = mt*128 + wm*32 + mi*16 + qr;
            int lcol = wn*32 + ni*8 + qc*2;
            float b0 = bias[ncol0 + lcol], b1 = bias[ncol0 + lcol + 1];
            long gcol = (long)nt*64 + lcol;
            if (row < 4912)
                *(float2*)&Cp[(long)row*1792 + gcol] =
                    make_float2(acc[mi][ni][0] + b0, acc[mi][ni][1] + b1);
            if (row + 8 < 4912)
                *(float2*)&Cp[(long)(row+8)*1792 + gcol] =
                    make_float2(acc[mi][ni][2] + b0, acc[mi][ni][3] + b1);
        }
    }
}

// ------- tf32 adjacency GEMM: C[b] = A(307x307) @ Bm[b](307xCOLS) -------
template<int COLS>
__global__ void __launch_bounds__(256, 2)
k_adj_mma(const float* __restrict__ A, const float* __restrict__ Bm,
          float* __restrict__ Cm)
{
    __shared__ float As[2][16][136];
    __shared__ float Bs[2][16][72];
    const float* Bp = Bm + (long)blockIdx.z * N_ * COLS;
    float*       Cp = Cm + (long)blockIdx.z * N_ * COLS;
    const int m0 = blockIdx.y * 128, n0 = blockIdx.x * 64;
    const int tid = threadIdx.x;
    const int warp = tid >> 5, lane = tid & 31;
    const int wm = warp >> 1, wn = warp & 1;
    const int qr = lane >> 2, qc = lane & 3;
    const int arow = tid >> 1, acol = (tid & 1) * 8;
    const int brow = tid >> 4, bcol = (tid & 15) * 4;
    const int gm = m0 + arow;
    float aR[8], bRv[4];

    auto loadA = [&](int k0){
        #pragma unroll
        for (int i = 0; i < 8; i++) {
            int gk = k0 + acol + i;
            aR[i] = (gm < N_ && gk < N_) ? A[gm*N_ + gk] : 0.f;
        }
    };
    auto loadB = [&](int k0){
        int gk = k0 + brow;
        if (gk < N_) {
            float4 t = *(const float4*)(Bp + (long)gk*COLS + n0 + bcol);
            bRv[0]=t.x; bRv[1]=t.y; bRv[2]=t.z; bRv[3]=t.w;
        } else { bRv[0]=bRv[1]=bRv[2]=bRv[3]=0.f; }
    };
    auto sts = [&](int buf){
        #pragma unroll
        for (int i = 0; i < 8; i++)
            As[buf][acol+i][arow] = __uint_as_float(f2tf32(aR[i]));
        float4 c;
        c.x = __uint_as_float(f2tf32(bRv[0])); c.y = __uint_as_float(f2tf32(bRv[1]));
        c.z = __uint_as_float(f2tf32(bRv[2])); c.w = __uint_as_float(f2tf32(bRv[3]));
        *(float4*)&Bs[buf][brow][bcol] = c;
    };

    loadA(0); loadB(0);
    sts(0);
    __syncthreads();

    float acc[2][4][4];
    #pragma unroll
    for (int mi = 0; mi < 2; mi++)
        #pragma unroll
        for (int ni = 0; ni < 4; ni++)
            #pragma unroll
            for (int j = 0; j < 4; j++) acc[mi][ni][j] = 0.f;

    int buf = 0;
    #pragma unroll 1
    for (int k0 = 0; k0 < N_; k0 += 16) {
        bool nxt = (k0 + 16 < N_);
        if (nxt) { loadA(k0+16); loadB(k0+16); }
        #pragma unroll
        for (int ks = 0; ks < 2; ks++) {
            int kb = ks * 8;
            uint32_t a[2][4], b[4][2];
            #pragma unroll
            for (int mi = 0; mi < 2; mi++) {
                int mrow = wm*32 + mi*16;
                a[mi][0] = __float_as_uint(As[buf][kb+qc  ][mrow+qr  ]);
                a[mi][1] = __float_as_uint(As[buf][kb+qc  ][mrow+qr+8]);
                a[mi][2] = __float_as_uint(As[buf][kb+qc+4][mrow+qr  ]);
                a[mi][3] = __float_as_uint(As[buf][kb+qc+4][mrow+qr+8]);
            }
            #pragma unroll
            for (int ni = 0; ni < 4; ni++) {
                int ncol = wn*32 + ni*8;
                b[ni][0] = __float_as_uint(Bs[buf][kb+qc  ][ncol+qr]);
                b[ni][1] = __float_as_uint(Bs[buf][kb+qc+4][ncol+qr]);
            }
            #pragma unroll
            for (int mi = 0; mi < 2; mi++)
                #pragma unroll
                for (int ni = 0; ni < 4; ni++)
                    MMA_TF32(acc[mi][ni], a[mi], b[ni]);
        }
        if (nxt) { sts(buf^1); __syncthreads(); buf ^= 1; }
    }

    #pragma unroll
    for (int mi = 0; mi < 2; mi++) {
        #pragma unroll
        for (int ni = 0; ni < 4; ni++) {
            int row = m0 + wm*32 + mi*16 + qr;
            int col = n0 + wn*32 + ni*8 + qc*2;
            if (row < N_)
                *(float2*)&Cp[(long)row*COLS + col] =
                    make_float2(acc[mi][ni][0], acc[mi][ni][1]);
            if (row + 8 < N_)
                *(float2*)&Cp[(long)(row+8)*COLS + col] =
                    make_float2(acc[mi][ni][2], acc[mi][ni][3]);
        }
    }
}

// ------- tf32 K=64 linear GEMM with fused A-producer / epilogue -------
template<int AMODE, int EMODE>
__global__ void __launch_bounds__(256, 2)
k_lin64(const float* __restrict__ A0, const float* __restrict__ A1,
        const float* __restrict__ A2, const float* __restrict__ A3,
        const float* __restrict__ clipv,
        long sA, const float* __restrict__ Bw, long sB,
        float* __restrict__ Cm, long sC, int M,
        const float* __restrict__ bias, const float* __restrict__ T1e)
{
    __shared__ float As[2][16][136];
    __shared__ float Bs[2][16][72];
    const long za = (long)blockIdx.z * sA;
    const float* Bp = Bw + (long)blockIdx.z * sB;
    float*       Cp = Cm + (long)blockIdx.z * sC;
    const int m0 = blockIdx.y * 128;
    const int tid = threadIdx.x;
    const int warp = tid >> 5, lane = tid & 31;
    const int wm = warp >> 1, wn = warp & 1;
    const int qr = lane >> 2, qc = lane & 3;
    const int arow = tid >> 1, acol = (tid & 1) * 8;
    const int brow = tid >> 4, bcol = (tid & 15) * 4;
    const int gm = m0 + arow;
    float cv = 0.f;
    if (AMODE == 1) cv = clipv[0];
    float aR[8]; float4 bRv;

    auto loadA = [&](int k0){
        if (gm < M) {
            long off = za + (long)gm*64 + k0 + acol;
            if (AMODE == 0) {
                float4 v0 = *(const float4*)(A0 + off);
                float4 v1 = *(const float4*)(A0 + off + 4);
                aR[0]=v0.x; aR[1]=v0.y; aR[2]=v0.z; aR[3]=v0.w;
                aR[4]=v1.x; aR[5]=v1.y; aR[6]=v1.z; aR[7]=v1.w;
            } else if (AMODE == 1) {
                float4 s0 = *(const float4*)(A0 + off);
                float4 s1 = *(const float4*)(A0 + off + 4);
                float4 n0 = *(const float4*)(A1 + off);
                float4 n1 = *(const float4*)(A1 + off + 4);
                float sv[8] = {s0.x,s0.y,s0.z,s0.w,s1.x,s1.y,s1.z,s1.w};
                float nv[8] = {n0.x,n0.y,n0.z,n0.w,n1.x,n1.y,n1.z,n1.w};
                #pragma unroll
                for (int i = 0; i < 8; i++)
                    aR[i] = fmaxf(fminf(sv[i], nv[i]+cv), nv[i]-cv);
            } else {
                float4 g0 = *(const float4*)(A0 + off);
                float4 g1 = *(const float4*)(A0 + off + 4);
                float4 l0 = *(const float4*)(A1 + off);
                float4 l1 = *(const float4*)(A1 + off + 4);
                float4 e0 = *(const float4*)(A2 + off);
                float4 e1 = *(const float4*)(A2 + off + 4);
                float4 r0 = *(const float4*)(A3 + off);
                float4 r1 = *(const float4*)(A3 + off + 4);
                float gv[8] = {g0.x,g0.y,g0.z,g0.w,g1.x,g1.y,g1.z,g1.w};
                float lv[8] = {l0.x,l0.y,l0.z,l0.w,l1.x,l1.y,l1.z,l1.w};
                float ev[8] = {e0.x,e0.y,e0.z,e0.w,e1.x,e1.y,e1.z,e1.w};
                float rv[8] = {r0.x,r0.y,r0.z,r0.w,r1.x,r1.y,r1.z,r1.w};
                #pragma unroll
                for (int i = 0; i < 8; i++){
                    float sa = sg(gv[i]), sb = sg(lv[i]), se = sg(ev[i]);
                    aR[i] = (gv[i]*(sb+se) + lv[i]*(se+sa) + ev[i]*(sb+sa)
                             + rv[i]) * (1.f/6.f);
                }
            }
        } else {
            #pragma unroll
            for (int i = 0; i < 8; i++) aR[i] = 0.f;
        }
    };
    auto loadB = [&](int k0){
        bRv = *(const float4*)(Bp + (long)(k0 + brow)*64 + bcol);
    };
    auto sts = [&](int buf){
        #pragma unroll
        for (int i = 0; i < 8; i++)
            As[buf][acol+i][arow] = __uint_as_float(f2tf32(aR[i]));
        float4 c;
        c.x = __uint_as_float(f2tf32(bRv.x)); c.y = __uint_as_float(f2tf32(bRv.y));
        c.z = __uint_as_float(f2tf32(bRv.z)); c.w = __uint_as_float(f2tf32(bRv.w));
        *(float4*)&Bs[buf][brow][bcol] = c;
    };

    loadA(0); loadB(0);
    sts(0);
    __syncthreads();

    float acc[2][4][4];
    #pragma unroll
    for (int mi = 0; mi < 2; mi++)
        #pragma unroll
        for (int ni = 0; ni < 4; ni++)
            #pragma unroll
            for (int j = 0; j < 4; j++) acc[mi][ni][j] = 0.f;

    int buf = 0;
    #pragma unroll
    for (int k0 = 0; k0 < 64; k0 += 16) {
        bool nxt = (k0 + 16 < 64);
        if (nxt) { loadA(k0+16); loadB(k0+16); }
        #pragma unroll
        for (int ks = 0; ks < 2; ks++) {
            int kb = ks * 8;
            uint32_t a[2][4], b[4][2];
            #pragma unroll
            for (int mi = 0; mi < 2; mi++) {
                int mrow = wm*32 + mi*16;
                a[mi][0] = __float_as_uint(As[buf][kb+qc  ][mrow+qr  ]);
                a[mi][1] = __float_as_uint(As[buf][kb+qc  ][mrow+qr+8]);
                a[mi][2] = __float_as_uint(As[buf][kb+qc+4][mrow+qr  ]);
                a[mi][3] = __float_as_uint(As[buf][kb+qc+4][mrow+qr+8]);
            }
            #pragma unroll
            for (int ni = 0; ni < 4; ni++) {
                int ncol = wn*32 + ni*8;
                b[ni][0] = __float_as_uint(Bs[buf][kb+qc  ][ncol+qr]);
                b[ni][1] = __float_as_uint(Bs[buf][kb+qc+4][ncol+qr]);
            }
            #pragma unroll
            for (int mi = 0; mi < 2; mi++)
                #pragma unroll
                for (int ni = 0; ni < 4; ni++)
                    MMA_TF32(acc[mi][ni], a[mi], b[ni]);
        }
        if (nxt) { sts(buf^1); __syncthreads(); buf ^= 1; }
    }

    #pragma unroll
    for (int mi = 0; mi < 2; mi++) {
        #pragma unroll
        for (int ni = 0; ni < 4; ni++) {
            int col = wn*32 + ni*8 + qc*2;
            float b0 = bias ? bias[col] : 0.f, b1 = bias ? bias[col+1] : 0.f;
            #pragma unroll
            for (int h = 0; h < 2; h++) {
                int row = m0 + wm*32 + mi*16 + qr + h*8;
                if (row >= M) continue;
                float v0 = acc[mi][ni][h*2+0] + b0;
                float v1 = acc[mi][ni][h*2+1] + b1;
                long off = (long)row*64 + col;
                if (EMODE == 1) {
                    float2 t = *(const float2*)(T1e + (long)row*64 + col);
                    v0 = fmaxf(sg(t.x) + v0, 0.f);
                    v1 = fmaxf(sg(t.y) + v1, 0.f);
                }
                *(float2*)&Cp[off] = make_float2(v0, v1);
            }
        }
    }
}

// ---------------- fp32 SGEMM (tiny P gemm, cols=12) ----------------
__global__ void k_gemm(const float* __restrict__ A, int lda, long sA,
                       const float* __restrict__ Bm, int ldb, long sB,
                       float* __restrict__ Cm, int ldc, long sC,
                       int M, int K, int cols, const float* __restrict__ bias)
{
    __shared__ __align__(16) float As[16][64];
    __shared__ __align__(16) float Bs[16][64];
    const float* Ap = A  + (long)blockIdx.z * sA;
    const float* Bp = Bm + (long)blockIdx.z * sB;
    float*       Cp = Cm + (long)blockIdx.z * sC;
    int m0 = blockIdx.y * 64, n0 = blockIdx.x * 64;
    int tid = threadIdx.x;
    int ty = tid >> 4, tx = tid & 15;
    int arow = tid >> 2, akq = (tid & 3) << 2;
    int brow = tid >> 4, bnq = (tid & 15) << 2;
    float acc[4][4] = {};
    for (int k0 = 0; k0 < K; k0 += 16) {
        int am = m0 + arow;
        #pragma unroll
        for (int i = 0; i < 4; i++) {
            int kk = k0 + akq + i;
            As[akq + i][arow] = (am < M && kk < K) ? Ap[(long)am * lda + kk] : 0.f;
        }
        int bk = k0 + brow;
        #pragma unroll
        for (int i = 0; i < 4; i++) {
            int bn = n0 + bnq + i;
            Bs[brow][bnq + i] = (bk < K && bn < cols) ? Bp[(long)bk * ldb + bn] : 0.f;
        }
        __syncthreads();
        #pragma unroll
        for (int k = 0; k < 16; k++) {
            float4 av = *(const float4*)&As[k][ty << 2];
            float4 bv = *(const float4*)&Bs[k][tx << 2];
            float ax[4] = {av.x, av.y, av.z, av.w};
            float bx[4] = {bv.x, bv.y, bv.z, bv.w};
            #pragma unroll
            for (int i = 0; i < 4; i++)
                #pragma unroll
                for (int j = 0; j < 4; j++)
                    acc[i][j] += ax[i] * bx[j];
        }
        __syncthreads();
    }
    #pragma unroll
    for (int i = 0; i < 4; i++) {
        int m = m0 + (ty << 2) + i;
        if (m >= M) continue;
        #pragma unroll
        for (int j = 0; j < 4; j++) {
            int n = n0 + (tx << 2) + j;
            if (n < cols) Cp[(long)m * ldc + n] = acc[i][j] + (bias ? bias[n] : 0.f);
        }
    }
}

// ---------------- small setup kernels ----------------
__global__ void k_A(const float* adj, const float* mask, float* A){
    int i = blockIdx.x * 256 + threadIdx.x;
    if (i < N_*N_) A[i] = adj[i] + mask[i];
}
__global__ void k_rs(const float* A, float* rs){
    int n = blockIdx.x * 32 + threadIdx.x;
    if (n < N_) { float s = 0; for (int j = 0; j < N_; j++) s += A[n*N_+j]; rs[n] = s; }
}
__global__ void k_W(const float* wn, const float* dn, const float* w3, const float* d3,
                    float* Wout){
    __shared__ float bufA[4096];
    __shared__ float bufB[4096];
    __shared__ float dd[64];
    int s = blockIdx.x;
    const float* w = (s == 0) ? wn : w3 + (s-1)*4096;
    const float* d = (s == 0) ? dn : d3 + (s-1)*64;
    int tid = threadIdx.x;
    for (int i = tid; i < 4096; i += 1024) bufA[i] = w[i];
    if (tid < 64) dd[tid] = fminf(fmaxf(d[tid], 0.f), 1.f);
    __syncthreads();
    int row = tid >> 4, j0 = (tid & 15) << 2;
    float a0[4] = {};
    for (int k = 0; k < 64; k++) {
        float wk = bufA[row*64 + k] * dd[k];
        #pragma unroll
        for (int j = 0; j < 4; j++) a0[j] += wk * bufA[(j0+j)*64 + k];
    }
    __syncthreads();
    #pragma unroll
    for (int j = 0; j < 4; j++) bufB[row*64 + j0 + j] = a0[j];
    __syncthreads();
    float a1[4] = {};
    for (int k = 0; k < 64; k++) {
        float m1 = bufB[row*64 + k];
        #pragma unroll
        for (int j = 0; j < 4; j++) a1[j] += m1 * bufB[k*64 + j0 + j];
    }
    __syncthreads();
    #pragma unroll
    for (int j = 0; j < 4; j++) bufA[row*64 + j0 + j] = a1[j];
    __syncthreads();
    float a2[4] = {};
    for (int k = 0; k < 64; k++) {
        float m2 = bufA[row*64 + k];
        #pragma unroll
        for (int j = 0; j < 4; j++) a2[j] += m2 * bufB[k*64 + j0 + j];
    }
    #pragma unroll
    for (int j = 0; j < 4; j++)
        Wout[s*4096 + row*64 + j0 + j] = 1.6f*bufB[row*64 + j0 + j] - 0.6f*a2[j];
}
__global__ void k_em(const float* __restrict__ x, const float* __restrict__ w3,
                     const float* __restrict__ w4,
                     float* em, float* u3, float* u4){
    __shared__ float xs[8][768];
    __shared__ float ems[8][12];
    int w = threadIdx.x >> 5, l = threadIdx.x & 31;
    int bn = blockIdx.x*8 + w;
    if (bn >= B_*N_) return;
    const float* xp = x + (long)bn*768;
    #pragma unroll
    for (int i = 0; i < 24; i++) xs[w][l + i*32] = xp[l + i*32];
    __syncwarp();
    if (l < 12) {
        float s = 0;
        #pragma unroll 8
        for (int c = 0; c < 64; c++) s += xs[w][l*64 + ((c + l) & 63)];
        s *= (1.f/64.f);
        ems[w][l] = s;
        em[bn*12 + l] = s;
    }
    __syncwarp();
    if (l < 12) {
        float s3 = 0, s4 = 0;
        #pragma unroll
        for (int tt = 0; tt < 12; tt++){ s3 += ems[w][tt]*w3[tt*12+l]; s4 += ems[w][tt]*w4[tt*12+l]; }
        u3[bn*12+l] = s3; u4[bn*12+l] = s4;
    }
}
// smem-staged k_S: one block per batch, coalesced loads, MLP-friendly accumulate
__global__ void __launch_bounds__(256)
k_S2(const float* __restrict__ u3, const float* __restrict__ u4,
     float* __restrict__ S3, float* __restrict__ S4, float* __restrict__ C34){
    int b = blockIdx.x;
    __shared__ float u3s[N_*12];
    __shared__ float u4s[N_*12];
    int tid = threadIdx.x;
    const float* p3 = u3 + (long)b*N_*12;
    const float* p4 = u4 + (long)b*N_*12;
    for (int i = tid; i < N_*12; i += 256){ u3s[i] = p3[i]; u4s[i] = p4[i]; }
    __syncthreads();
    if (tid < 144){
        int o = tid/12, p = tid%12;
        float c = 0, s3 = 0, s4 = 0;
        #pragma unroll 4
        for (int n = 0; n < N_; n++){
            float a = u3s[n*12+o], r = u4s[n*12+p];
            c += a*r;
            if (p == 0) s3 += a;
            if (o == 0) s4 += r;
        }
        C34[b*144+tid] = c;
        if (p == 0) S3[b*12+o] = s3;
        if (o == 0) S4[b*12+p] = s4;
    }
}
__global__ void k_attE(const float* u3, const float* u4, const float* S3, const float* S4,
                       const float* C34, const float* P, const float* em,
                       const float* alphaE, float* attE, float* coefE){
    int bn = blockIdx.x; int b = bn / N_; int n = bn % N_;
    int tid = threadIdx.x;
    int o = tid/12, p = tid%12;
    __shared__ float at[144], ems[12];
    float l = (float)N_*u3[bn*12+o]*u4[bn*12+p] + u3[bn*12+o]*S4[b*12+p]
            + S3[b*12+o]*u4[bn*12+p] + C34[b*144+tid];
    float a = sg(l);
    at[tid] = a; attE[(long)bn*144+tid] = a;
    if (tid < 12) ems[tid] = em[bn*12+tid];
    __syncthreads();
    if (tid < 12) {
        float wv = 0;
        #pragma unroll
        for (int oo = 0; oo < 12; oo++) wv += ems[oo]*at[oo*12+tid];
        coefE[bn*12+tid] = 0.5f*sg(alphaE[n])*P[bn*12+tid] + wv;
    }
}
__global__ void k_base(const float* coefE, const float* fw, float* base){
    int b = blockIdx.y, t = blockIdx.x, c = threadIdx.x;
    float s = 0;
    #pragma unroll 4
    for (int n = 0; n < N_; n++) s += fw[n*64+c] * coefE[(b*N_+n)*12+t];
    base[(b*12+t)*64+c] = s;
}
__global__ void k_R(const float* attE, const float* fw, float* R){
    int b = blockIdx.y, tp = blockIdx.x, c = threadIdx.x;
    float s = 0;
    #pragma unroll 4
    for (int n = 0; n < N_; n++) s += attE[((long)b*N_+n)*144+tp] * fw[n*64+c];
    R[((long)b*144+tp)*64+c] = s;
}
__global__ void k_g0(const float* fw, const float* alphaE, const float* rs, float* g0){
    int c = threadIdx.x; float s = 0;
    for (int n = 0; n < N_; n++) s += fw[n*64+c]*sg(alphaE[n])*rs[n];
    g0[c] = 0.5f*s;
}
__global__ void k_al(const float* x, const float* w3, const float* w4,
                     float* al, float* ar){
    __shared__ float w3s[144], w4s[144];
    int bn = blockIdx.x, c = threadIdx.x;
    for (int i = c; i < 144; i += 64){ w3s[i] = w3[i]; w4s[i] = w4[i]; }
    __syncthreads();
    float xr[12];
    const float* xp = x + (long)bn*768 + c;
    #pragma unroll
    for (int t = 0; t < 12; t++) xr[t] = xp[t*64];
    #pragma unroll
    for (int o = 0; o < 12; o++){
        float a = 0, r = 0;
        #pragma unroll
        for (int t = 0; t < 12; t++){ a += xr[t]*w3s[t*12+o]; r += xr[t]*w4s[t*12+o]; }
        al[((long)bn*12+o)*64+c] = a; ar[((long)bn*12+o)*64+c] = r;
    }
}
__global__ void k_attN(const float* al, const float* ar, float* attN){
    int c = blockIdx.x, b = blockIdx.y;
    int tid = threadIdx.x;
    int o = tid/12, p = tid%12;
    __shared__ float alc[32*12], arc[32*12];
    float acc = 0;
    for (int n0 = 0; n0 < N_; n0 += 32){
        int cnt = min(32, N_ - n0);
        __syncthreads();
        for (int i = tid; i < cnt*12; i += 144){
            int nn = i/12, oo = i%12;
            long base = (((long)b*N_ + n0 + nn)*12 + oo)*64 + c;
            alc[i] = al[base]; arc[i] = ar[base];
        }
        __syncthreads();
        for (int i = 0; i < cnt; i++) acc += alc[i*12+o]*arc[i*12+p];
    }
    attN[((long)b*64+c)*144 + tid] = sg(acc);
}
__global__ void k_x0n(const float* x, const float* Sn, const float* xw,
                      const float* attN, const float* alphaN, float* x0n){
    int bn = blockIdx.x; int b = bn / N_, n = bn % N_;
    int c = threadIdx.x;
    __shared__ float xs[12][64];
    const float* xp = x + (long)bn*768;
    #pragma unroll
    for (int t = 0; t < 12; t++) xs[t][c] = xp[t*64+c];
    __syncthreads();
    float aN = 0.5f*sg(alphaN[n]);
    const float* an = attN + ((long)b*64+c)*144;
    #pragma unroll
    for (int o = 0; o < 12; o++){
        float tn = 0;
        #pragma unroll
        for (int p = 0; p < 12; p++) tn += an[o*12+p]*xs[p][c];
        long idx = (long)bn*768 + o*64 + c;
        x0n[idx] = aN*Sn[idx] + tn + xw[idx] - xs[o][c];
    }
}
__global__ void k_mhsa(const float* qkv, float* z0, float* z){
    int h = blockIdx.x, b = blockIdx.y;
    __shared__ __align__(16) float Ks[N_*DK_];
    __shared__ __align__(16) float Vs[N_*DV_];
    int tid = threadIdx.x;
    for (int i = tid; i < N_*DK_; i += 256){
        int n = i/DK_, d = i%DK_;
        Ks[i] = qkv[((long)b*N_+n)*1792 + 768 + h*DK_ + d];
    }
    for (int i = tid; i < N_*DV_; i += 256){
        int n = i/DV_, d = i%DV_;
        Vs[i] = qkv[((long)b*N_+n)*1792 + 1536 + h*DV_ + d];
    }
    __syncthreads();
    const float4* K4 = (const float4*)Ks;
    const float4* V4 = (const float4*)Vs;
    for (int r = 0; r < 2; r++){
        int n = tid + r*256;
        if (n >= N_) break;
        float qr[DK_];
        const float* qp = qkv + ((long)b*N_+n)*1792 + h*DK_;
        #pragma unroll
        for (int d = 0; d < DK_; d++) qr[d] = qp[d];
        float mmax = -1e30f, l = 0.f, acc[DV_] = {};
        for (int m = 0; m < N_; m++){
            float s = 0;
            #pragma unroll
            for (int i = 0; i < 6; i++){
                float4 kv = K4[m*6+i];
                s += qr[i*4+0]*kv.x + qr[i*4+1]*kv.y + qr[i*4+2]*kv.z + qr[i*4+3]*kv.w;
            }
            s *= NORM_;
            float nm = fmaxf(mmax, s);
            float e0 = __expf(mmax - nm);
            float e1 = __expf(s - nm);
            l = l*e0 + e1;
            float4 v0 = V4[m*2+0], v1 = V4[m*2+1];
            acc[0] = acc[0]*e0 + e1*v0.x; acc[1] = acc[1]*e0 + e1*v0.y;
            acc[2] = acc[2]*e0 + e1*v0.z; acc[3] = acc[3]*e0 + e1*v0.w;
            acc[4] = acc[4]*e0 + e1*v1.x; acc[5] = acc[5]*e0 + e1*v1.y;
            acc[6] = acc[6]*e0 + e1*v1.z; acc[7] = acc[7]*e0 + e1*v1.w;
            mmax = nm;
        }
        float inv = 1.f/l;
        #pragma unroll
        for (int j = 0; j < DV_; j++){
            int flat = h*DV_ + j;
            int g = flat >> 6, c = flat & 63;
            long idx = (((long)g*B_+b)*N_+n)*64 + c;
            float val = acc[j]*inv;
            z0[idx] = val; z[idx] = val;
        }
    }
}
__global__ void k_att3(const float* z, const float* w31, const float* w41, float* att3){
    int gb = blockIdx.x, c = threadIdx.x;
    float s = 0;
    const float* zp = z + (long)gb*N_*64 + c;
    #pragma unroll 4
    for (int n = 0; n < N_; n++){ float v = zp[n*64]; s += v*v; }
    att3[gb*64+c] = sg(w31[0]*w41[0]*s);
}
__global__ void k_step(const float* zin, const float* Sz, const float* zw,
                       const float* z0, const float* att3, const float* alpha3,
                       float* zout, float* x1s, int step){
    long idx = (long)blockIdx.x*256 + threadIdx.x;
    if (idx >= G4) return;
    int c = idx & 63;
    long r = idx >> 6;
    int n = r % N_; long r2 = r / N_;
    int b = r2 % B_; int g = (int)(r2 / B_);
    float zv = zin[idx];
    float out = 0.5f*sg(alpha3[g*N_+n])*Sz[idx] + att3[(g*B_+b)*64+c]*zv
              + zw[idx] + z0[idx] - 2.f*zv;
    zout[idx] = out;
    x1s[(((long)b*N_+n)*12 + step*4 + g)*64 + c] = out;
}
__global__ void k_xe(const float* em, const float* base, const float* g0,
                     const float* R, const float* fb, float* xe){
    int bm = blockIdx.x; int b = bm / N_;
    int c = threadIdx.x;
    float emr[12];
    #pragma unroll
    for (int t = 0; t < 12; t++) emr[t] = em[bm*12+t];
    float g0c = g0[c], fbc = fb[c];
    #pragma unroll
    for (int t = 0; t < 12; t++){
        float acc = base[(b*12+t)*64+c] + emr[t]*g0c + fbc;
        #pragma unroll
        for (int tp = 0; tp < 12; tp++)
            acc += emr[tp]*R[((long)b*144 + tp*12 + t)*64 + c];
        xe[((long)bm*12+t)*64+c] = acc;
    }
}

// ---------------- host ----------------
static void gemmF(const float* A, int lda, long sA, const float* B, int ldb, long sB,
                  float* C, int ldc, long sC, int M, int K, int cols,
                  const float* bias, int batch){
    dim3 g((cols+63)/64, (M+63)/64, batch);
    k_gemm<<<g, 256>>>(A, lda, sA, B, ldb, sB, C, ldc, sC, M, K, cols, bias);
}

extern "C" void kernel_launch(void* const* d_in, const int* in_sizes, int n_in,
                              void* d_out, int out_size){
    const float* x      = (const float*)d_in[0];
    const float* adj    = (const float*)d_in[1];
    const float* mask   = (const float*)d_in[2];
    const float* w3_12  = (const float*)d_in[3];
    const float* w4_12  = (const float*)d_in[4];
    const float* w3_1   = (const float*)d_in[5];
    const float* w4_1   = (const float*)d_in[6];
    const float* alphaN = (const float*)d_in[7];
    const float* w_n11  = (const float*)d_in[8];
    const float* d_n11  = (const float*)d_in[9];
    const float* alphaE = (const float*)d_in[10];
    const float* alpha3 = (const float*)d_in[11];
    const float* w_3    = (const float*)d_in[12];
    const float* d_3    = (const float*)d_in[13];
    const float* wq     = (const float*)d_in[14];
    const float* bq     = (const float*)d_in[15];
    const float* wk     = (const float*)d_in[16];
    const float* bk     = (const float*)d_in[17];
    const float* wv     = (const float*)d_in[18];
    const float* bv     = (const float*)d_in[19];
    const float* fc1w   = (const float*)d_in[20];
    const float* fc1b   = (const float*)d_in[21];
    const float* fc2w   = (const float*)d_in[22];
    const float* fc2b   = (const float*)d_in[23];
    const float* fcew   = (const float*)d_in[24];
    const float* fceb   = (const float*)d_in[25];
    const float* clip   = (const float*)d_in[26];
    float* out = (float*)d_out;

    float* S;
    cudaGetSymbolAddress((void**)&S, g_s);
    float *A = S+O_A, *RS = S+O_RS, *W = S+O_W, *EM = S+O_EM, *U3 = S+O_U3, *U4 = S+O_U4;
    float *P = S+O_P, *S3 = S+O_S3, *S4 = S+O_S4, *C34 = S+O_C34, *ATTE = S+O_ATTE;
    float *COEFE = S+O_COEFE, *BASE = S+O_BASE, *R = S+O_R, *G0 = S+O_G0, *SN = S+O_SN;
    float *AL = S+O_AL, *AR = S+O_AR, *ATTN = S+O_ATTN, *XW = S+O_XW, *X0N = S+O_X0N;
    float *QKV = S+O_QKV, *Z0 = S+O_Z0, *Z = S+O_Z;
    float *SZ = S+O_SZ, *ZW = S+O_ZW, *ATT3 = S+O_ATT3, *X1S = S+O_X1S;
    float *XG = S+O_XG, *XL = S+O_XL, *XE = S+O_XE, *T1 = S+O_T1;

    const int MROWS = B_*N_*T_;               // 58944
    dim3 gLin(1, (MROWS+127)/128, 1);

    k_A<<<(N_*N_+255)/256, 256>>>(adj, mask, A);
    k_rs<<<(N_+31)/32, 32>>>(A, RS);
    k_W<<<5, 1024>>>(w_n11, d_n11, w_3, d_3, W);
    k_em<<<(B_*N_+7)/8, 256>>>(x, w3_12, w4_12, EM, U3, U4);
    k_S2<<<B_, 256>>>(U3, U4, S3, S4, C34);
    gemmF(A, N_, 0, EM, 12, (long)N_*12, P, 12, (long)N_*12, N_, N_, 12, nullptr, B_);
    k_attE<<<B_*N_, 144>>>(U3, U4, S3, S4, C34, P, EM, alphaE, ATTE, COEFE);
    k_base<<<dim3(12, B_), 64>>>(COEFE, fcew, BASE);
    k_R<<<dim3(144, B_), 64>>>(ATTE, fcew, R);
    k_g0<<<1, 64>>>(fcew, alphaE, RS, G0);
    k_adj_mma<768><<<dim3(12, 3, 16), 256>>>(A, x, SN);
    k_lin64<0,0><<<gLin, 256>>>(x, nullptr, nullptr, nullptr, nullptr,
                                0, W, 0, XW, 0, MROWS, nullptr, nullptr);
    k_al<<<B_*N_, 64>>>(x, w3_12, w4_12, AL, AR);
    k_attN<<<dim3(64, B_), 144>>>(AL, AR, ATTN);
    k_x0n<<<B_*N_, 64>>>(x, SN, XW, ATTN, alphaN, X0N);
    k_qkv_mma<<<dim3(28, 39), 256>>>(x, wq, wk, wv, bq, bk, bv, QKV);
    k_mhsa<<<dim3(NH_, B_), 256>>>(QKV, Z0, Z);
    for (int step = 0; step < 3; step++){
        k_adj_mma<64><<<dim3(1, 3, 64), 256>>>(A, Z, SZ);
        k_lin64<0,0><<<dim3(1, (B_*N_+127)/128, 4), 256>>>(
            Z, nullptr, nullptr, nullptr, nullptr,
            16L*N_*64, W + 4096, 4096, ZW, 16L*N_*64, B_*N_, nullptr, nullptr);
        k_att3<<<64, 64>>>(Z, w3_1, w4_1, ATT3);
        k_step<<<(int)((G4+255)/256), 256>>>(Z, SZ, ZW, Z0, ATT3, alpha3, Z, X1S, step);
    }
    // XG = clip(X1S, X0N +- clip) @ fc1w + fc1b   (clip fused)
    k_lin64<1,0><<<gLin, 256>>>(X1S, X0N, nullptr, nullptr, clip,
                                0, fc1w, 0, XG, 0, MROWS, fc1b, nullptr);
    // XL = X0N @ fc1w + fc1b
    k_lin64<0,0><<<gLin, 256>>>(X0N, nullptr, nullptr, nullptr, nullptr,
                                0, fc1w, 0, XL, 0, MROWS, fc1b, nullptr);
    k_xe<<<B_*N_, 64>>>(EM, BASE, G0, R, fceb, XE);
    // T1 = x @ fc2w + fc2b
    k_lin64<0,0><<<gLin, 256>>>(x, nullptr, nullptr, nullptr, nullptr,
                                0, fc2w, 0, T1, 0, MROWS, fc2b, nullptr);
    // out = relu(sg(T1) + final1(XG,XL,XE,x) @ fc2w + fc2b)
    k_lin64<2,1><<<gLin, 256>>>(XG, XL, XE, x, nullptr,
                                0, fc2w, 0, out, 0, MROWS, fc2b, T1);
}